// round 10
// baseline (speedup 1.0000x reference)
#include <cuda_runtime.h>
#include <cstdint>
#include <cstddef>

typedef unsigned long long ull;

#define S_LEN    2048
#define BATCH    32
#define HID      256
#define CLUSTER  8
#define N_CLUST  16
#define GRID_REC (CLUSTER * N_CLUST)   // 128

// ---------------- device scratch (no allocations allowed) ----------------
__device__ float g_Xc[(size_t)65536 * 1024];   // [s][b][col] : 256 MB, x@Wx + b

// ---------------- activations (accurate fast paths) ----------------
__device__ __forceinline__ float fsigm(float x) {
    return 1.0f / (1.0f + __expf(-x));
}
__device__ __forceinline__ float ftanh(float x) {
    x = fminf(9.0f, fmaxf(-9.0f, x));
    float e = __expf(-2.0f * x);
    return __fdividef(1.0f - e, 1.0f + e);
}

// ---------------- packed fp32x2 helpers ----------------
__device__ __forceinline__ ull ffma2(ull a, ull b, ull c) {
    ull d;
    asm("fma.rn.f32x2 %0, %1, %2, %3;" : "=l"(d) : "l"(a), "l"(b), "l"(c));
    return d;
}
__device__ __forceinline__ float f2sum(ull v) {
    float lo = __uint_as_float((unsigned)(v & 0xffffffffull));
    float hi = __uint_as_float((unsigned)(v >> 32));
    return lo + hi;
}
__device__ __forceinline__ ull fpack(float lo, float hi) {
    return ((ull)__float_as_uint(hi) << 32) | (ull)__float_as_uint(lo);
}
__device__ __forceinline__ float f2lo(ull v) {
    return __uint_as_float((unsigned)(v & 0xffffffffull));
}
__device__ __forceinline__ float f2hi(ull v) {
    return __uint_as_float((unsigned)(v >> 32));
}

// ---------------- phase 1: Xc[s][b][col] = x[b][s][:] @ W[:256][col] + bias[col] ----------------
// M = 65536 rows ordered r = s*32 + b ; N = 1024 ; K = 256. FFMA2 mainloop.
__global__ void __launch_bounds__(256, 2) gemm_x_kernel(const float* __restrict__ x,
                                                        const float* __restrict__ W,
                                                        const float* __restrict__ bias) {
    __shared__ ull   As2[8][132];  // k-major, A values pre-duplicated as f32x2 (padded)
    __shared__ float Bs[8][128];
    const int tid = threadIdx.x;
    const int rt = blockIdx.x, ct = blockIdx.y;

    const int a_ri = tid >> 1, a_kq = (tid & 1) << 2;
    const int row  = rt * 128 + a_ri;            // r = s*32 + b
    const float* a_src = x + (size_t)(row & 31) * (S_LEN * 256)
                           + (size_t)(row >> 5) * 256 + a_kq;
    const int b_kr = tid >> 5, b_c4 = (tid & 31) << 2;
    const float* b_src = W + (size_t)b_kr * 1024 + ct * 128 + b_c4;

    const int ry = tid >> 4, cx = tid & 15;
    ull acc2[8][4];
#pragma unroll
    for (int i = 0; i < 8; i++)
#pragma unroll
        for (int j = 0; j < 4; j++) acc2[i][j] = 0ull;

    for (int kb = 0; kb < 256; kb += 8) {
        float4 av = *(const float4*)(a_src + kb);
        float4 bv = *(const float4*)(b_src + (size_t)kb * 1024);
        __syncthreads();
        As2[a_kq + 0][a_ri] = fpack(av.x, av.x);
        As2[a_kq + 1][a_ri] = fpack(av.y, av.y);
        As2[a_kq + 2][a_ri] = fpack(av.z, av.z);
        As2[a_kq + 3][a_ri] = fpack(av.w, av.w);
        *(float4*)&Bs[b_kr][b_c4] = bv;
        __syncthreads();
#pragma unroll
        for (int k = 0; k < 8; k++) {
            ull ar2[8];
            ull br2[4];
            *(ulonglong2*)(ar2)     = *(const ulonglong2*)&As2[k][ry * 8];
            *(ulonglong2*)(ar2 + 2) = *(const ulonglong2*)&As2[k][ry * 8 + 2];
            *(ulonglong2*)(ar2 + 4) = *(const ulonglong2*)&As2[k][ry * 8 + 4];
            *(ulonglong2*)(ar2 + 6) = *(const ulonglong2*)&As2[k][ry * 8 + 6];
            *(ulonglong2*)(br2)     = *(const ulonglong2*)&Bs[k][cx * 8];
            *(ulonglong2*)(br2 + 2) = *(const ulonglong2*)&Bs[k][cx * 8 + 4];
#pragma unroll
            for (int i = 0; i < 8; i++)
#pragma unroll
                for (int j = 0; j < 4; j++)
                    acc2[i][j] = ffma2(ar2[i], br2[j], acc2[i][j]);
        }
    }

    float bb[8];
#pragma unroll
    for (int j = 0; j < 8; j++) bb[j] = bias[ct * 128 + cx * 8 + j];

    // coalesced epilogue: [s][b][col] layout -> row-major [r][col], float4 stores
#pragma unroll
    for (int i = 0; i < 8; i++) {
        int r = rt * 128 + ry * 8 + i;
        float* dst = g_Xc + (size_t)r * 1024 + ct * 128 + cx * 8;
        float4 v0, v1;
        v0.x = f2lo(acc2[i][0]) + bb[0]; v0.y = f2hi(acc2[i][0]) + bb[1];
        v0.z = f2lo(acc2[i][1]) + bb[2]; v0.w = f2hi(acc2[i][1]) + bb[3];
        v1.x = f2lo(acc2[i][2]) + bb[4]; v1.y = f2hi(acc2[i][2]) + bb[5];
        v1.z = f2lo(acc2[i][3]) + bb[6]; v1.w = f2hi(acc2[i][3]) + bb[7];
        *(float4*)dst = v0;
        *(float4*)(dst + 4) = v1;
    }
}

// ---------------- init: zero the two tail tensors of the output ----------------
__global__ void init_kernel(float* __restrict__ out) {
    int t = blockIdx.x * blockDim.x + threadIdx.x;   // 4096 threads
    float* tail = out + (size_t)BATCH * S_LEN * HID;
    for (int idx = t; idx < 2 * BATCH * HID; idx += 4096) tail[idx] = 0.0f;
}

// ---------------- phase 2: cluster-local recurrence (DSMEM data-flag sync) ----------------
// 16 clusters x 8 CTAs. Cluster cl owns batches {2cl, 2cl+1}. CTA rank owns
// hidden units n in [32*rank, 32*rank+32) -> 128 gate-cols, Wh REGISTER-resident.
// h in smem (double buffered). Per step: pushers write h-pair u64 + release-flag
// (value s+1) into all 8 peers; each of 256 threads spin-acquires exactly ONE
// flag in its own smem. No barrier.cluster in the loop -> no per-step L1 flush.
__global__ void __launch_bounds__(256, 1) __cluster_dims__(CLUSTER, 1, 1)
lstm_rec_kernel(const float* __restrict__ W,
                const float* __restrict__ h0,
                const float* __restrict__ c0,
                float* __restrict__ out) {
    __shared__ __align__(16) ull h2s[2][128][2];   // [buf][k2][b] : 4 KB
    __shared__ float red[2][2][128];               // [kh][bl][c]  : 2 KB, conflict-free
    __shared__ unsigned flagsA[256];               // [rank*32 + bl*16 + pair] : 1 KB

    const int tid  = threadIdx.x;
    const int cb   = blockIdx.x;
    const int rank = cb & (CLUSTER - 1);
    const int cl   = cb >> 3;
    const int b0g  = cl * 2;                       // first global batch of this cluster

    // ---- dot mapping: c = local col (0..127), kh = k-half (0/1) ----
    const int c   = tid & 127;
    const int kh  = tid >> 7;                      // uniform per warp
    const int g   = c >> 5;
    const int n   = rank * 32 + (c & 31);
    const int colg = g * 256 + n;

    // ---- register-resident Wh slice: 64 k-pairs for (colg, kh) ----
    ull w[64];
#pragma unroll
    for (int j = 0; j < 64; j++) {
        int k = 256 + kh * 128 + 2 * j;
        w[j] = fpack(W[(size_t)k * 1024 + colg],
                     W[(size_t)(k + 1) * 1024 + colg]);
    }

    // ---- owner mapping (gates + c/h update): 64 threads = 32 n x 2 b ----
    const bool owner = (tid < 64);
    const int o_nl = tid & 31;
    const int o_bl = (tid >> 5) & 1;
    const int o_n  = rank * 32 + o_nl;
    const int o_bg = b0g + o_bl;
    float c_reg = owner ? c0[o_bg * HID + o_n] : 0.0f;

    // ---- DSMEM addresses: peer h2s slots + peer flag slots ----
    uint32_t hbase = (uint32_t)__cvta_generic_to_shared(&h2s[0][0][0]);
    uint32_t fbase = (uint32_t)__cvta_generic_to_shared(&flagsA[0]);
    uint32_t peer_h[CLUSTER], peer_f[CLUSTER];
    const uint32_t h_off = (uint32_t)((((rank * 16) + (o_nl >> 1)) * 2 + o_bl) * 8);
    const uint32_t f_off = (uint32_t)((rank * 32 + o_bl * 16 + (o_nl >> 1)) * 4);
#pragma unroll
    for (int r = 0; r < CLUSTER; r++) {
        uint32_t ra, rf;
        asm("mapa.shared::cluster.u32 %0, %1, %2;" : "=r"(ra) : "r"(hbase), "r"(r));
        asm("mapa.shared::cluster.u32 %0, %1, %2;" : "=r"(rf) : "r"(fbase), "r"(r));
        peer_h[r] = ra + h_off;
        peer_f[r] = rf + f_off;
    }
    // my poll slot (own smem)
    const uint32_t my_flag = fbase + (uint32_t)tid * 4;

    // ---- init: flags + h buffer 0 ----
    flagsA[tid] = 0u;
    {
        int k2 = tid >> 1, bb = tid & 1;           // 256 entries, one per thread
        h2s[0][k2][bb] = fpack(h0[(b0g + bb) * HID + 2 * k2],
                               h0[(b0g + bb) * HID + 2 * k2 + 1]);
    }
    __syncthreads();
    // one-time cluster sync: peers' flags + h buffers must exist before use
    asm volatile("barrier.cluster.arrive.aligned;" ::: "memory");
    asm volatile("barrier.cluster.wait.aligned;" ::: "memory");

    // ---- Xc prefetch for step 0 (owners: 4 gate values) ----
    float xc0 = 0.f, xc1 = 0.f, xc2 = 0.f, xc3 = 0.f;
    if (owner) {
        const float* xp = g_Xc + (size_t)o_bg * 1024 + o_n;
        xc0 = xp[0]; xc1 = xp[256]; xc2 = xp[512]; xc3 = xp[768];
    }

    for (int s = 0; s < S_LEN; s++) {
        // ---- dots: 64 k-pairs/thread, weights in regs, h broadcast LDS.128 ----
        const ulonglong2* hptr = (const ulonglong2*)&h2s[s & 1][kh * 64][0];
        ull acc0 = 0ull, acc1 = 0ull;
#pragma unroll
        for (int j = 0; j < 64; j++) {
            ulonglong2 hv = hptr[j];               // [b0 pair, b1 pair] : uniform addr
            acc0 = ffma2(w[j], hv.x, acc0);
            acc1 = ffma2(w[j], hv.y, acc1);
        }
        red[kh][0][c] = f2sum(acc0);               // conflict-free (stride 1 in c)
        red[kh][1][c] = f2sum(acc1);
        __syncthreads();

        // ---- owners: gates, activations, c/h update, push h + release flags ----
        if (owner) {
            float z0 = red[0][o_bl][o_nl]       + red[1][o_bl][o_nl]       + xc0;
            float z1 = red[0][o_bl][32 + o_nl]  + red[1][o_bl][32 + o_nl]  + xc1;
            float z2 = red[0][o_bl][64 + o_nl]  + red[1][o_bl][64 + o_nl]  + xc2;
            float z3 = red[0][o_bl][96 + o_nl]  + red[1][o_bl][96 + o_nl]  + xc3;
            z0 = ftanh(z0); z1 = ftanh(z1); z2 = ftanh(z2); z3 = ftanh(z3);  // quirk: tanh first
            float iv = fsigm(z0);
            float fv = fsigm(z1);
            float gv = ftanh(z2);
            float ov = fsigm(z3);
            c_reg = fv * c_reg + iv * gv;
            float hv = ftanh(c_reg) * ov;

            // pack k-pair (even n = lo, odd n = hi); even lanes push u64 + flag
            float hv_hi = __shfl_xor_sync(0xffffffffu, hv, 1);
            if ((o_nl & 1) == 0) {
                ull hp = fpack(hv, hv_hi);
                uint32_t boff = (uint32_t)(((s & 1) ^ 1) * sizeof(h2s[0]));
                unsigned fval = (unsigned)(s + 1);
#pragma unroll
                for (int r = 0; r < CLUSTER; r++) {
                    asm volatile("st.shared::cluster.u64 [%0], %1;"
                                 :: "r"(peer_h[r] + boff), "l"(hp) : "memory");
                    // release: orders the h store above before the flag for acquirers
                    asm volatile("st.release.cluster.shared::cluster.b32 [%0], %1;"
                                 :: "r"(peer_f[r]), "r"(fval) : "memory");
                }
            }
            out[(size_t)o_bg * (S_LEN * HID) + (size_t)s * HID + o_n] = hv;
        }

        // ---- prefetch next step's Xc while waiting ----
        if (owner && s + 1 < S_LEN) {
            const float* xp = g_Xc + (size_t)(s + 1) * 32768 + (size_t)o_bg * 1024 + o_n;
            xc0 = xp[0]; xc1 = xp[256]; xc2 = xp[512]; xc3 = xp[768];
        }

        // ---- wait: each thread acquires exactly one flag in its OWN smem ----
        {
            unsigned target = (unsigned)(s + 1);
            unsigned v;
            do {
                asm volatile("ld.acquire.cluster.shared::cta.b32 %0, [%1];"
                             : "=r"(v) : "r"(my_flag) : "memory");
            } while (v < target);
        }
        __syncthreads();   // all flags (and thus all h data) observed CTA-wide
    }
}

// ---------------- launch ----------------
extern "C" void kernel_launch(void* const* d_in, const int* in_sizes, int n_in,
                              void* d_out, int out_size) {
    const float* x    = (const float*)d_in[0];   // (32,2048,256)
    const float* h0   = (const float*)d_in[1];   // (1,32,256)
    const float* c0   = (const float*)d_in[2];   // (1,32,256)
    const float* W    = (const float*)d_in[3];   // (512,1024)
    const float* bias = (const float*)d_in[4];   // (1024,)
    float* out = (float*)d_out;                  // (32,2048,256) + 2*(1,32,256) zeros

    gemm_x_kernel<<<dim3(512, 8, 1), 256>>>(x, W, bias);
    init_kernel<<<16, 256>>>(out);
    lstm_rec_kernel<<<GRID_REC, 256>>>(W, h0, c0, out);
}

// round 11
// speedup vs baseline: 2.7353x; 2.7353x over previous
#include <cuda_runtime.h>
#include <cstdint>
#include <cstddef>

typedef unsigned long long ull;

#define S_LEN    2048
#define BATCH    32
#define HID      256
#define CLUSTER  8
#define N_CLUST  16
#define GRID_REC (CLUSTER * N_CLUST)   // 128

// ---------------- device scratch (no allocations allowed) ----------------
__device__ float g_Xc[(size_t)65536 * 1024];   // [s][b][col] : 256 MB, x@Wx + b

// ---------------- activations (accurate fast paths) ----------------
__device__ __forceinline__ float fsigm(float x) {
    return 1.0f / (1.0f + __expf(-x));
}
__device__ __forceinline__ float ftanh(float x) {
    x = fminf(9.0f, fmaxf(-9.0f, x));
    float e = __expf(-2.0f * x);
    return __fdividef(1.0f - e, 1.0f + e);
}

// ---------------- packed fp32x2 helpers ----------------
__device__ __forceinline__ ull ffma2(ull a, ull b, ull c) {
    ull d;
    asm("fma.rn.f32x2 %0, %1, %2, %3;" : "=l"(d) : "l"(a), "l"(b), "l"(c));
    return d;
}
__device__ __forceinline__ float f2sum(ull v) {
    float lo = __uint_as_float((unsigned)(v & 0xffffffffull));
    float hi = __uint_as_float((unsigned)(v >> 32));
    return lo + hi;
}
__device__ __forceinline__ ull fpack(float lo, float hi) {
    return ((ull)__float_as_uint(hi) << 32) | (ull)__float_as_uint(lo);
}
__device__ __forceinline__ float f2lo(ull v) {
    return __uint_as_float((unsigned)(v & 0xffffffffull));
}
__device__ __forceinline__ float f2hi(ull v) {
    return __uint_as_float((unsigned)(v >> 32));
}

// ---------------- phase 1: Xc[s][b][col] = x[b][s][:] @ W[:256][col] + bias[col] ----------------
// M = 65536 rows ordered r = s*32 + b ; N = 1024 ; K = 256. FFMA2 mainloop.
__global__ void __launch_bounds__(256, 2) gemm_x_kernel(const float* __restrict__ x,
                                                        const float* __restrict__ W,
                                                        const float* __restrict__ bias) {
    __shared__ ull   As2[8][132];  // k-major, A values pre-duplicated as f32x2 (padded)
    __shared__ float Bs[8][128];
    const int tid = threadIdx.x;
    const int rt = blockIdx.x, ct = blockIdx.y;

    const int a_ri = tid >> 1, a_kq = (tid & 1) << 2;
    const int row  = rt * 128 + a_ri;            // r = s*32 + b
    const float* a_src = x + (size_t)(row & 31) * (S_LEN * 256)
                           + (size_t)(row >> 5) * 256 + a_kq;
    const int b_kr = tid >> 5, b_c4 = (tid & 31) << 2;
    const float* b_src = W + (size_t)b_kr * 1024 + ct * 128 + b_c4;

    const int ry = tid >> 4, cx = tid & 15;
    ull acc2[8][4];
#pragma unroll
    for (int i = 0; i < 8; i++)
#pragma unroll
        for (int j = 0; j < 4; j++) acc2[i][j] = 0ull;

    for (int kb = 0; kb < 256; kb += 8) {
        float4 av = *(const float4*)(a_src + kb);
        float4 bv = *(const float4*)(b_src + (size_t)kb * 1024);
        __syncthreads();
        As2[a_kq + 0][a_ri] = fpack(av.x, av.x);
        As2[a_kq + 1][a_ri] = fpack(av.y, av.y);
        As2[a_kq + 2][a_ri] = fpack(av.z, av.z);
        As2[a_kq + 3][a_ri] = fpack(av.w, av.w);
        *(float4*)&Bs[b_kr][b_c4] = bv;
        __syncthreads();
#pragma unroll
        for (int k = 0; k < 8; k++) {
            ull ar2[8];
            ull br2[4];
            *(ulonglong2*)(ar2)     = *(const ulonglong2*)&As2[k][ry * 8];
            *(ulonglong2*)(ar2 + 2) = *(const ulonglong2*)&As2[k][ry * 8 + 2];
            *(ulonglong2*)(ar2 + 4) = *(const ulonglong2*)&As2[k][ry * 8 + 4];
            *(ulonglong2*)(ar2 + 6) = *(const ulonglong2*)&As2[k][ry * 8 + 6];
            *(ulonglong2*)(br2)     = *(const ulonglong2*)&Bs[k][cx * 8];
            *(ulonglong2*)(br2 + 2) = *(const ulonglong2*)&Bs[k][cx * 8 + 4];
#pragma unroll
            for (int i = 0; i < 8; i++)
#pragma unroll
                for (int j = 0; j < 4; j++)
                    acc2[i][j] = ffma2(ar2[i], br2[j], acc2[i][j]);
        }
    }

    float bb[8];
#pragma unroll
    for (int j = 0; j < 8; j++) bb[j] = bias[ct * 128 + cx * 8 + j];

    // coalesced epilogue: [s][b][col] layout -> row-major [r][col], float4 stores
#pragma unroll
    for (int i = 0; i < 8; i++) {
        int r = rt * 128 + ry * 8 + i;
        float* dst = g_Xc + (size_t)r * 1024 + ct * 128 + cx * 8;
        float4 v0, v1;
        v0.x = f2lo(acc2[i][0]) + bb[0]; v0.y = f2hi(acc2[i][0]) + bb[1];
        v0.z = f2lo(acc2[i][1]) + bb[2]; v0.w = f2hi(acc2[i][1]) + bb[3];
        v1.x = f2lo(acc2[i][2]) + bb[4]; v1.y = f2hi(acc2[i][2]) + bb[5];
        v1.z = f2lo(acc2[i][3]) + bb[6]; v1.w = f2hi(acc2[i][3]) + bb[7];
        *(float4*)dst = v0;
        *(float4*)(dst + 4) = v1;
    }
}

// ---------------- init: zero the two tail tensors of the output ----------------
__global__ void init_kernel(float* __restrict__ out) {
    int t = blockIdx.x * blockDim.x + threadIdx.x;   // 4096 threads
    float* tail = out + (size_t)BATCH * S_LEN * HID;
    for (int idx = t; idx < 2 * BATCH * HID; idx += 4096) tail[idx] = 0.0f;
}

// ---------------- phase 2: cluster-local recurrence (R7 protocol: barrier.cluster) ----------------
// 16 clusters x 8 CTAs. Cluster cl owns batches {2cl, 2cl+1}. CTA rank owns
// hidden units n in [32*rank, 32*rank+32) -> 128 gate-cols, Wh REGISTER-resident.
// h in smem (double buffered); new h pushed via packed u64 DSMEM stores (even
// lanes); per-step sync = barrier.cluster arrive ... wait, with out-store and
// Xc prefetch hidden between arrive and wait.
__global__ void __launch_bounds__(256, 1) __cluster_dims__(CLUSTER, 1, 1)
lstm_rec_kernel(const float* __restrict__ W,
                const float* __restrict__ h0,
                const float* __restrict__ c0,
                float* __restrict__ out) {
    __shared__ __align__(16) ull h2s[2][128][2];   // [buf][k2][b] : 4 KB
    __shared__ float red[2][2][128];               // [kh][bl][c]  : 2 KB, conflict-free

    const int tid  = threadIdx.x;
    const int cb   = blockIdx.x;
    const int rank = cb & (CLUSTER - 1);
    const int cl   = cb >> 3;
    const int b0g  = cl * 2;                       // first global batch of this cluster

    // ---- dot mapping: c = local col (0..127), kh = k-half (0/1) ----
    const int c   = tid & 127;
    const int kh  = tid >> 7;                      // uniform per warp
    const int n   = rank * 32 + (c & 31);
    const int colg = (c >> 5) * 256 + n;

    // ---- register-resident Wh slice: 64 k-pairs for (colg, kh) ----
    ull w[64];
#pragma unroll
    for (int j = 0; j < 64; j++) {
        int k = 256 + kh * 128 + 2 * j;
        w[j] = fpack(W[(size_t)k * 1024 + colg],
                     W[(size_t)(k + 1) * 1024 + colg]);
    }

    // ---- owner mapping (gates + c/h update): 64 threads = 32 n x 2 b ----
    const bool owner = (tid < 64);
    const int o_nl = tid & 31;
    const int o_bl = (tid >> 5) & 1;
    const int o_n  = rank * 32 + o_nl;
    const int o_bg = b0g + o_bl;
    float c_reg = owner ? c0[o_bg * HID + o_n] : 0.0f;

    // ---- DSMEM addresses: peer h2s u64 slots (even owner lanes push pairs) ----
    uint32_t hbase = (uint32_t)__cvta_generic_to_shared(&h2s[0][0][0]);
    uint32_t peer_h[CLUSTER];
    const uint32_t h_off = (uint32_t)((((rank * 16) + (o_nl >> 1)) * 2 + o_bl) * 8);
#pragma unroll
    for (int r = 0; r < CLUSTER; r++) {
        uint32_t ra;
        asm("mapa.shared::cluster.u32 %0, %1, %2;" : "=r"(ra) : "r"(hbase), "r"(r));
        peer_h[r] = ra + h_off;
    }

    // ---- init h2s buf0 (full h, both batches) from h0 ----
    {
        int k2 = tid >> 1, bb = tid & 1;           // 256 entries, one per thread
        h2s[0][k2][bb] = fpack(h0[(b0g + bb) * HID + 2 * k2],
                               h0[(b0g + bb) * HID + 2 * k2 + 1]);
    }

    // ---- Xc prefetch for step 0 (owners: 4 gate values) ----
    float xc0 = 0.f, xc1 = 0.f, xc2 = 0.f, xc3 = 0.f;
    if (owner) {
        const float* xp = g_Xc + (size_t)o_bg * 1024 + o_n;
        xc0 = xp[0]; xc1 = xp[256]; xc2 = xp[512]; xc3 = xp[768];
    }
    __syncthreads();
    asm volatile("barrier.cluster.arrive.aligned;" ::: "memory");
    asm volatile("barrier.cluster.wait.aligned;" ::: "memory");

    for (int s = 0; s < S_LEN; s++) {
        // ---- dots: 64 k-pairs/thread, weights in regs, h broadcast LDS.128 ----
        const ulonglong2* hptr = (const ulonglong2*)&h2s[s & 1][kh * 64][0];
        ull acc0 = 0ull, acc1 = 0ull;
#pragma unroll
        for (int j = 0; j < 64; j++) {
            ulonglong2 hv = hptr[j];               // [b0 pair, b1 pair] : uniform addr
            acc0 = ffma2(w[j], hv.x, acc0);
            acc1 = ffma2(w[j], hv.y, acc1);
        }
        red[kh][0][c] = f2sum(acc0);               // conflict-free (stride 1 in c)
        red[kh][1][c] = f2sum(acc1);
        __syncthreads();

        // ---- owners: gates, activations, c/h update, push h (packed u64) ----
        float hv = 0.0f;
        if (owner) {
            float z0 = red[0][o_bl][o_nl]       + red[1][o_bl][o_nl]       + xc0;
            float z1 = red[0][o_bl][32 + o_nl]  + red[1][o_bl][32 + o_nl]  + xc1;
            float z2 = red[0][o_bl][64 + o_nl]  + red[1][o_bl][64 + o_nl]  + xc2;
            float z3 = red[0][o_bl][96 + o_nl]  + red[1][o_bl][96 + o_nl]  + xc3;
            z0 = ftanh(z0); z1 = ftanh(z1); z2 = ftanh(z2); z3 = ftanh(z3);  // quirk: tanh first
            float iv = fsigm(z0);
            float fv = fsigm(z1);
            float gv = ftanh(z2);
            float ov = fsigm(z3);
            c_reg = fv * c_reg + iv * gv;
            hv = ftanh(c_reg) * ov;

            // pack k-pair (even n = lo, odd n = hi); even lanes push u64 to 8 CTAs
            float hv_hi = __shfl_xor_sync(0xffffffffu, hv, 1);
            if ((o_nl & 1) == 0) {
                ull hp = fpack(hv, hv_hi);
                uint32_t boff = (uint32_t)(((s & 1) ^ 1) * sizeof(h2s[0]));
#pragma unroll
                for (int r = 0; r < CLUSTER; r++)
                    asm volatile("st.shared::cluster.u64 [%0], %1;"
                                 :: "r"(peer_h[r] + boff), "l"(hp) : "memory");
            }
        }

        // arrive releases the DSMEM pushes; hide out-store + prefetch before wait
        asm volatile("barrier.cluster.arrive.aligned;" ::: "memory");
        if (owner) {
            out[(size_t)o_bg * (S_LEN * HID) + (size_t)s * HID + o_n] = hv;
            if (s + 1 < S_LEN) {
                const float* xp = g_Xc + (size_t)(s + 1) * 32768 + (size_t)o_bg * 1024 + o_n;
                xc0 = xp[0]; xc1 = xp[256]; xc2 = xp[512]; xc3 = xp[768];
            }
        }
        asm volatile("barrier.cluster.wait.aligned;" ::: "memory");
    }
}

// ---------------- launch ----------------
extern "C" void kernel_launch(void* const* d_in, const int* in_sizes, int n_in,
                              void* d_out, int out_size) {
    const float* x    = (const float*)d_in[0];   // (32,2048,256)
    const float* h0   = (const float*)d_in[1];   // (1,32,256)
    const float* c0   = (const float*)d_in[2];   // (1,32,256)
    const float* W    = (const float*)d_in[3];   // (512,1024)
    const float* bias = (const float*)d_in[4];   // (1024,)
    float* out = (float*)d_out;                  // (32,2048,256) + 2*(1,32,256) zeros

    gemm_x_kernel<<<dim3(512, 8, 1), 256>>>(x, W, bias);
    init_kernel<<<16, 256>>>(out);
    lstm_rec_kernel<<<GRID_REC, 256>>>(W, h0, c0, out);
}

// round 16
// speedup vs baseline: 2.8122x; 1.0281x over previous
#include <cuda_runtime.h>
#include <cstdint>
#include <cstddef>

typedef unsigned long long ull;

#define S_LEN    2048
#define HALF_S   1024
#define BATCH    32
#define HID      256
#define CLUSTER  8
#define N_CLUST  16
#define GRID_REC 152   // 19 clusters; 3 are dummies (>=148 avoids low-grid throttle)

// ---------------- device scratch (no allocations allowed) ----------------
__device__ float g_Xc[(size_t)65536 * 1024];   // [s][b][col] : 256 MB, x@Wx + b
__device__ float g_hstate[BATCH * HID];        // h handoff between rec halves
__device__ float g_cstate[BATCH * HID];        // c handoff between rec halves

// ---------------- activations (accurate fast paths) ----------------
__device__ __forceinline__ float fsigm(float x) {
    return 1.0f / (1.0f + __expf(-x));
}
__device__ __forceinline__ float ftanh(float x) {
    x = fminf(9.0f, fmaxf(-9.0f, x));
    float e = __expf(-2.0f * x);
    return __fdividef(1.0f - e, 1.0f + e);
}

// ---------------- packed fp32x2 helpers ----------------
__device__ __forceinline__ ull ffma2(ull a, ull b, ull c) {
    ull d;
    asm("fma.rn.f32x2 %0, %1, %2, %3;" : "=l"(d) : "l"(a), "l"(b), "l"(c));
    return d;
}
__device__ __forceinline__ float f2sum(ull v) {
    float lo = __uint_as_float((unsigned)(v & 0xffffffffull));
    float hi = __uint_as_float((unsigned)(v >> 32));
    return lo + hi;
}
__device__ __forceinline__ ull fpack(float lo, float hi) {
    return ((ull)__float_as_uint(hi) << 32) | (ull)__float_as_uint(lo);
}

// ---------------- phase 1: Xc[s][b][col] = x[b][s][:] @ W[:256][col] + bias[col] ----------------
// M = 65536 rows ordered r = s*32 + b ; N = 1024 ; K = 256. (measured 773us config)
__global__ void __launch_bounds__(256, 2) gemm_x_kernel(const float* __restrict__ x,
                                                        const float* __restrict__ W,
                                                        const float* __restrict__ bias) {
    __shared__ float As[8][132];   // k-major, padded (conflict-free)
    __shared__ float Bs[8][128];
    const int tid = threadIdx.x;
    const int rt = blockIdx.x, ct = blockIdx.y;

    const int a_ri = tid >> 1, a_kq = (tid & 1) << 2;
    const int row  = rt * 128 + a_ri;            // r = s*32 + b
    const float* a_src = x + (size_t)(row & 31) * (S_LEN * 256)
                           + (size_t)(row >> 5) * 256 + a_kq;
    const int b_kr = tid >> 5, b_c4 = (tid & 31) << 2;
    const float* b_src = W + (size_t)b_kr * 1024 + ct * 128 + b_c4;

    const int ry = tid >> 4, cx = tid & 15;
    float acc[8][8];
#pragma unroll
    for (int i = 0; i < 8; i++)
#pragma unroll
        for (int j = 0; j < 8; j++) acc[i][j] = 0.0f;

    for (int kb = 0; kb < 256; kb += 8) {
        float4 av = *(const float4*)(a_src + kb);
        float4 bv = *(const float4*)(b_src + (size_t)kb * 1024);
        __syncthreads();
        As[a_kq + 0][a_ri] = av.x;
        As[a_kq + 1][a_ri] = av.y;
        As[a_kq + 2][a_ri] = av.z;
        As[a_kq + 3][a_ri] = av.w;
        *(float4*)&Bs[b_kr][b_c4] = bv;
        __syncthreads();
#pragma unroll
        for (int k = 0; k < 8; k++) {
            float ar[8], br[8];
            *(float4*)(ar)     = *(const float4*)&As[k][ry * 8];
            *(float4*)(ar + 4) = *(const float4*)&As[k][ry * 8 + 4];
            *(float4*)(br)     = *(const float4*)&Bs[k][cx * 8];
            *(float4*)(br + 4) = *(const float4*)&Bs[k][cx * 8 + 4];
#pragma unroll
            for (int i = 0; i < 8; i++)
#pragma unroll
                for (int j = 0; j < 8; j++)
                    acc[i][j] = fmaf(ar[i], br[j], acc[i][j]);
        }
    }

    float bb[8];
#pragma unroll
    for (int j = 0; j < 8; j++) bb[j] = bias[ct * 128 + cx * 8 + j];

    // coalesced epilogue: [s][b][col] layout -> row-major [r][col], float4 stores
#pragma unroll
    for (int i = 0; i < 8; i++) {
        int r = rt * 128 + ry * 8 + i;
        float* dst = g_Xc + (size_t)r * 1024 + ct * 128 + cx * 8;
        float4 v0, v1;
        v0.x = acc[i][0] + bb[0]; v0.y = acc[i][1] + bb[1];
        v0.z = acc[i][2] + bb[2]; v0.w = acc[i][3] + bb[3];
        v1.x = acc[i][4] + bb[4]; v1.y = acc[i][5] + bb[5];
        v1.z = acc[i][6] + bb[6]; v1.w = acc[i][7] + bb[7];
        *(float4*)dst = v0;
        *(float4*)(dst + 4) = v1;
    }
}

// ---------------- init: zero the two tail tensors of the output ----------------
__global__ void init_kernel(float* __restrict__ out) {
    int t = blockIdx.x * blockDim.x + threadIdx.x;   // 4096 threads
    float* tail = out + (size_t)BATCH * S_LEN * HID;
    for (int idx = t; idx < 2 * BATCH * HID; idx += 4096) tail[idx] = 0.0f;
}

// ---------------- phase 2: cluster-local recurrence (R7 protocol, half-sequence) ----------------
// 16 real clusters x 8 CTAs (+3 dummy clusters that exit). Cluster cl owns
// batches {2cl, 2cl+1}. CTA rank owns hidden units [32*rank, 32*rank+32) ->
// 128 gate-cols, Wh REGISTER-resident. h in smem (double buffered); new h via
// packed u64 DSMEM pushes; per-step sync = barrier.cluster arrive/wait. Runs
// steps [s0, s0+HALF_S); h/c state read from (h_src,c_src), final state written
// to (g_hstate, g_cstate).
__global__ void __launch_bounds__(256, 1) __cluster_dims__(CLUSTER, 1, 1)
lstm_rec_kernel(const float* __restrict__ W,
                const float* __restrict__ h_src,
                const float* __restrict__ c_src,
                float* __restrict__ out,
                int s0) {
    __shared__ __align__(16) ull h2s[2][128][2];   // [buf][k2][b] : 4 KB
    __shared__ float red[2][2][128];               // [kh][bl][c]  : 2 KB, conflict-free

    const int tid  = threadIdx.x;
    const int cb   = blockIdx.x;
    const int rank = cb & (CLUSTER - 1);
    const int cl   = cb >> 3;
    if (cl >= N_CLUST) return;                     // dummy clusters (grid pad) exit whole
    const int b0g  = cl * 2;                       // first global batch of this cluster

    // ---- dot mapping: c = local col (0..127), kh = k-half (0/1) ----
    const int c   = tid & 127;
    const int kh  = tid >> 7;                      // uniform per warp
    const int colg = (c >> 5) * 256 + rank * 32 + (c & 31);

    // ---- register-resident Wh slice: 64 k-pairs for (colg, kh) ----
    ull w[64];
#pragma unroll
    for (int j = 0; j < 64; j++) {
        int k = 256 + kh * 128 + 2 * j;
        w[j] = fpack(W[(size_t)k * 1024 + colg],
                     W[(size_t)(k + 1) * 1024 + colg]);
    }

    // ---- owner mapping (gates + c/h update): 64 threads = 32 n x 2 b ----
    const bool owner = (tid < 64);
    const int o_nl = tid & 31;
    const int o_bl = (tid >> 5) & 1;
    const int o_n  = rank * 32 + o_nl;
    const int o_bg = b0g + o_bl;
    float c_reg = owner ? c_src[o_bg * HID + o_n] : 0.0f;

    // ---- DSMEM addresses: peer h2s u64 slots (even owner lanes push pairs) ----
    uint32_t hbase = (uint32_t)__cvta_generic_to_shared(&h2s[0][0][0]);
    uint32_t peer_h[CLUSTER];
    const uint32_t h_off = (uint32_t)((((rank * 16) + (o_nl >> 1)) * 2 + o_bl) * 8);
#pragma unroll
    for (int r = 0; r < CLUSTER; r++) {
        uint32_t ra;
        asm("mapa.shared::cluster.u32 %0, %1, %2;" : "=r"(ra) : "r"(hbase), "r"(r));
        peer_h[r] = ra + h_off;
    }

    // ---- init h2s buf0 (full h, both batches) from h_src ([32][256] layout) ----
    {
        int k2 = tid >> 1, bb = tid & 1;           // 256 entries, one per thread
        h2s[0][k2][bb] = fpack(h_src[(b0g + bb) * HID + 2 * k2],
                               h_src[(b0g + bb) * HID + 2 * k2 + 1]);
    }

    // ---- Xc prefetch for first step (owners: 4 gate values) ----
    float xc0 = 0.f, xc1 = 0.f, xc2 = 0.f, xc3 = 0.f;
    if (owner) {
        const float* xp = g_Xc + (size_t)s0 * 32768 + (size_t)o_bg * 1024 + o_n;
        xc0 = xp[0]; xc1 = xp[256]; xc2 = xp[512]; xc3 = xp[768];
    }
    __syncthreads();
    asm volatile("barrier.cluster.arrive.aligned;" ::: "memory");
    asm volatile("barrier.cluster.wait.aligned;" ::: "memory");

    float hv = 0.0f;
    for (int t = 0; t < HALF_S; t++) {
        const int s = s0 + t;
        // ---- dots: 64 k-pairs/thread, weights in regs, h broadcast LDS.128 ----
        const ulonglong2* hptr = (const ulonglong2*)&h2s[t & 1][kh * 64][0];
        ull acc0 = 0ull, acc1 = 0ull;
#pragma unroll
        for (int j = 0; j < 64; j++) {
            ulonglong2 hvv = hptr[j];              // [b0 pair, b1 pair] : uniform addr
            acc0 = ffma2(w[j], hvv.x, acc0);
            acc1 = ffma2(w[j], hvv.y, acc1);
        }
        red[kh][0][c] = f2sum(acc0);               // conflict-free (stride 1 in c)
        red[kh][1][c] = f2sum(acc1);
        __syncthreads();

        // ---- owners: gates, activations, c/h update, push h (packed u64) ----
        if (owner) {
            float z0 = red[0][o_bl][o_nl]       + red[1][o_bl][o_nl]       + xc0;
            float z1 = red[0][o_bl][32 + o_nl]  + red[1][o_bl][32 + o_nl]  + xc1;
            float z2 = red[0][o_bl][64 + o_nl]  + red[1][o_bl][64 + o_nl]  + xc2;
            float z3 = red[0][o_bl][96 + o_nl]  + red[1][o_bl][96 + o_nl]  + xc3;
            z0 = ftanh(z0); z1 = ftanh(z1); z2 = ftanh(z2); z3 = ftanh(z3);  // quirk: tanh first
            float iv = fsigm(z0);
            float fv = fsigm(z1);
            float gv = ftanh(z2);
            float ov = fsigm(z3);
            c_reg = fv * c_reg + iv * gv;
            hv = ftanh(c_reg) * ov;

            // pack k-pair (even n = lo, odd n = hi); even lanes push u64 to 8 CTAs
            float hv_hi = __shfl_xor_sync(0xffffffffu, hv, 1);
            if ((o_nl & 1) == 0) {
                ull hp = fpack(hv, hv_hi);
                uint32_t boff = (uint32_t)(((t & 1) ^ 1) * sizeof(h2s[0]));
#pragma unroll
                for (int r = 0; r < CLUSTER; r++)
                    asm volatile("st.shared::cluster.u64 [%0], %1;"
                                 :: "r"(peer_h[r] + boff), "l"(hp) : "memory");
            }
        }

        // arrive releases the DSMEM pushes; hide out-store + prefetch before wait
        asm volatile("barrier.cluster.arrive.aligned;" ::: "memory");
        if (owner) {
            out[(size_t)o_bg * (S_LEN * HID) + (size_t)s * HID + o_n] = hv;
            if (s + 1 < S_LEN) {
                const float* xp = g_Xc + (size_t)(s + 1) * 32768 + (size_t)o_bg * 1024 + o_n;
                xc0 = xp[0]; xc1 = xp[256]; xc2 = xp[512]; xc3 = xp[768];
            }
        }
        asm volatile("barrier.cluster.wait.aligned;" ::: "memory");
    }

    // ---- state handoff for the next half ----
    if (owner) {
        g_hstate[o_bg * HID + o_n] = hv;
        g_cstate[o_bg * HID + o_n] = c_reg;
    }
}

// ---------------- launch ----------------
extern "C" void kernel_launch(void* const* d_in, const int* in_sizes, int n_in,
                              void* d_out, int out_size) {
    const float* x    = (const float*)d_in[0];   // (32,2048,256)
    const float* h0   = (const float*)d_in[1];   // (1,32,256)
    const float* c0   = (const float*)d_in[2];   // (1,32,256)
    const float* W    = (const float*)d_in[3];   // (512,1024)
    const float* bias = (const float*)d_in[4];   // (1024,)
    float* out = (float*)d_out;                  // (32,2048,256) + 2*(1,32,256) zeros

    float* hstate;
    float* cstate;
    cudaGetSymbolAddress((void**)&hstate, g_hstate);
    cudaGetSymbolAddress((void**)&cstate, g_cstate);

    gemm_x_kernel<<<dim3(512, 8, 1), 256>>>(x, W, bias);
    init_kernel<<<16, 256>>>(out);
    lstm_rec_kernel<<<GRID_REC, 256>>>(W, h0, c0, out, 0);
    lstm_rec_kernel<<<GRID_REC, 256>>>(W, hstate, cstate, out, HALF_S);
}